// round 12
// baseline (speedup 1.0000x reference)
#include <cuda_runtime.h>
#include <cuda_bf16.h>
#include <math.h>
#include <stdint.h>

#define Tn 2048
#define Dn 1024
#define Hn 4096
#define Ln 8
#define Vn 50257
#define VP 50304
#define EPSn 1e-5f

// ---------------- scratch (no allocations allowed) ----------------
__device__ float g_x [Tn*Dn];
__device__ float g_xn[Tn*Dn];
__device__ float g_xk[Tn*Dn];
__device__ float g_xv[Tn*Dn];
__device__ float g_xr[Tn*Dn];
__device__ float g_k [Tn*Dn];
__device__ float g_v [Tn*Dn];
__device__ float g_r [Tn*Dn];
__device__ float g_ry[Tn*Dn];
__device__ float g_rr[Tn*Dn];
__device__ float g_kk[Tn*Hn];
__device__ float g_hw[(size_t)Dn * VP];   // padded head weight (fp32)

// ---------------- PTX helpers (portable PTX only) ----------------
__device__ __forceinline__ uint32_t smem_u32(const void* p) {
    uint32_t a;
    asm("{ .reg .u64 t; cvta.to.shared.u64 t, %1; cvt.u32.u64 %0, t; }" : "=r"(a) : "l"(p));
    return a;
}

#define LDSM_X4(addr, r0, r1, r2, r3) \
    asm volatile("ldmatrix.sync.aligned.m8n8.x4.shared.b16 {%0,%1,%2,%3}, [%4];" \
        : "=r"(r0), "=r"(r1), "=r"(r2), "=r"(r3) : "r"(addr))

#define LDSM_X4T(addr, r0, r1, r2, r3) \
    asm volatile("ldmatrix.sync.aligned.m8n8.x4.trans.shared.b16 {%0,%1,%2,%3}, [%4];" \
        : "=r"(r0), "=r"(r1), "=r"(r2), "=r"(r3) : "r"(addr))

__device__ __forceinline__ void mma_bf16(float* c, const uint32_t* a,
                                         uint32_t b0, uint32_t b1) {
    asm volatile(
        "mma.sync.aligned.m16n8k16.row.col.f32.bf16.bf16.f32 "
        "{%0,%1,%2,%3}, {%4,%5,%6,%7}, {%8,%9}, {%0,%1,%2,%3};"
        : "+f"(c[0]), "+f"(c[1]), "+f"(c[2]), "+f"(c[3])
        : "r"(a[0]), "r"(a[1]), "r"(a[2]), "r"(a[3]), "r"(b0), "r"(b1));
}

__device__ __forceinline__ void sts4(uint32_t addr, uint32_t a, uint32_t b,
                                     uint32_t c, uint32_t d) {
    asm volatile("st.shared.v4.b32 [%0], {%1,%2,%3,%4};"
                 :: "r"(addr), "r"(a), "r"(b), "r"(c), "r"(d) : "memory");
}

// split (x,y) into bf16 hi/lo pairs packed as bf16x2 words
__device__ __forceinline__ void split2(float x, float y, uint32_t& h, uint32_t& l) {
    __nv_bfloat16 hx = __float2bfloat16_rn(x);
    __nv_bfloat16 hy = __float2bfloat16_rn(y);
    float rx = x - __bfloat162float(hx);
    float ry = y - __bfloat162float(hy);
    __nv_bfloat162 hp; hp.x = hx; hp.y = hy;
    __nv_bfloat162 lp; lp.x = __float2bfloat16_rn(rx); lp.y = __float2bfloat16_rn(ry);
    h = *reinterpret_cast<uint32_t*>(&hp);
    l = *reinterpret_cast<uint32_t*>(&lp);
}

// ---------------- LayerNorm (fp32 out; optional embedding gather) ------------
__global__ void __launch_bounds__(256)
ln_kernel(const float* __restrict__ x, const int* __restrict__ tokens,
          const float* __restrict__ w, const float* __restrict__ b,
          float* __restrict__ y)
{
    __shared__ float sh0[8], sh1[8];
    int t = blockIdx.x;
    const float* row;
    if (tokens) row = x + (size_t)tokens[t] * Dn;
    else        row = x + (size_t)t * Dn;

    float4 vv = reinterpret_cast<const float4*>(row)[threadIdx.x];
    float s  = vv.x + vv.y + vv.z + vv.w;
    float s2 = vv.x*vv.x + vv.y*vv.y + vv.z*vv.z + vv.w*vv.w;
    #pragma unroll
    for (int o = 16; o > 0; o >>= 1) {
        s  += __shfl_down_sync(0xffffffffu, s,  o);
        s2 += __shfl_down_sync(0xffffffffu, s2, o);
    }
    int wid = threadIdx.x >> 5, lid = threadIdx.x & 31;
    if (lid == 0) { sh0[wid] = s; sh1[wid] = s2; }
    __syncthreads();
    if (threadIdx.x < 32) {
        s  = (lid < 8) ? sh0[lid] : 0.f;
        s2 = (lid < 8) ? sh1[lid] : 0.f;
        #pragma unroll
        for (int o = 4; o > 0; o >>= 1) {
            s  += __shfl_down_sync(0xffffffffu, s,  o);
            s2 += __shfl_down_sync(0xffffffffu, s2, o);
        }
        if (lid == 0) { sh0[0] = s; sh1[0] = s2; }
    }
    __syncthreads();
    float mu  = sh0[0] * (1.f / Dn);
    float var = sh1[0] * (1.f / Dn) - mu * mu;
    float rstd = rsqrtf(var + EPSn);

    float4 wv = reinterpret_cast<const float4*>(w)[threadIdx.x];
    float4 bv = reinterpret_cast<const float4*>(b)[threadIdx.x];
    float4 o4;
    o4.x = (vv.x - mu) * rstd * wv.x + bv.x;
    o4.y = (vv.y - mu) * rstd * wv.y + bv.y;
    o4.z = (vv.z - mu) * rstd * wv.z + bv.z;
    o4.w = (vv.w - mu) * rstd * wv.w + bv.w;
    reinterpret_cast<float4*>(y + (size_t)t * Dn)[threadIdx.x] = o4;
}

// ------------- dual-row LN reduce helper (cur & prev in one pass) ------------
__device__ __forceinline__ void ln2_stats(float4 cur, float4 prv,
                                          float& mu_c, float& rs_c,
                                          float& mu_p, float& rs_p)
{
    __shared__ float sh[4][8];
    float sc  = cur.x + cur.y + cur.z + cur.w;
    float s2c = cur.x*cur.x + cur.y*cur.y + cur.z*cur.z + cur.w*cur.w;
    float sp  = prv.x + prv.y + prv.z + prv.w;
    float s2p = prv.x*prv.x + prv.y*prv.y + prv.z*prv.z + prv.w*prv.w;
    #pragma unroll
    for (int o = 16; o > 0; o >>= 1) {
        sc  += __shfl_down_sync(0xffffffffu, sc,  o);
        s2c += __shfl_down_sync(0xffffffffu, s2c, o);
        sp  += __shfl_down_sync(0xffffffffu, sp,  o);
        s2p += __shfl_down_sync(0xffffffffu, s2p, o);
    }
    int wid = threadIdx.x >> 5, lid = threadIdx.x & 31;
    if (lid == 0) { sh[0][wid] = sc; sh[1][wid] = s2c; sh[2][wid] = sp; sh[3][wid] = s2p; }
    __syncthreads();
    if (threadIdx.x < 32) {
        sc  = (lid < 8) ? sh[0][lid] : 0.f;
        s2c = (lid < 8) ? sh[1][lid] : 0.f;
        sp  = (lid < 8) ? sh[2][lid] : 0.f;
        s2p = (lid < 8) ? sh[3][lid] : 0.f;
        #pragma unroll
        for (int o = 4; o > 0; o >>= 1) {
            sc  += __shfl_down_sync(0xffffffffu, sc,  o);
            s2c += __shfl_down_sync(0xffffffffu, s2c, o);
            sp  += __shfl_down_sync(0xffffffffu, sp,  o);
            s2p += __shfl_down_sync(0xffffffffu, s2p, o);
        }
        if (lid == 0) { sh[0][0] = sc; sh[1][0] = s2c; sh[2][0] = sp; sh[3][0] = s2p; }
    }
    __syncthreads();
    mu_c = sh[0][0] * (1.f / Dn);
    rs_c = rsqrtf(sh[1][0] * (1.f / Dn) - mu_c * mu_c + EPSn);
    mu_p = sh[2][0] * (1.f / Dn);
    rs_p = rsqrtf(sh[3][0] * (1.f / Dn) - mu_p * mu_p + EPSn);
}

// ---------------- fused LN1 + time-mix3 (fp32 outputs) -----------------------
__global__ void __launch_bounds__(256)
lnmix3_kernel(const float* __restrict__ xin,
              const float* __restrict__ w, const float* __restrict__ b,
              const float* __restrict__ mk, const float* __restrict__ mv,
              const float* __restrict__ mr, float* __restrict__ xres)
{
    int t = blockIdx.x;
    float4 cur = reinterpret_cast<const float4*>(xin + (size_t)t * Dn)[threadIdx.x];
    float4 prv = make_float4(0.f, 0.f, 0.f, 0.f);
    if (t > 0) prv = reinterpret_cast<const float4*>(xin + (size_t)(t - 1) * Dn)[threadIdx.x];
    float mu_c, rs_c, mu_p, rs_p;
    ln2_stats(cur, prv, mu_c, rs_c, mu_p, rs_p);

    float4 wv = reinterpret_cast<const float4*>(w)[threadIdx.x];
    float4 bv = reinterpret_cast<const float4*>(b)[threadIdx.x];
    float o0 = (cur.x - mu_c) * rs_c * wv.x + bv.x;
    float o1 = (cur.y - mu_c) * rs_c * wv.y + bv.y;
    float o2 = (cur.z - mu_c) * rs_c * wv.z + bv.z;
    float o3 = (cur.w - mu_c) * rs_c * wv.w + bv.w;
    float fp = (t > 0) ? 1.f : 0.f;
    float p0 = fp * ((prv.x - mu_p) * rs_p * wv.x + bv.x);
    float p1 = fp * ((prv.y - mu_p) * rs_p * wv.y + bv.y);
    float p2 = fp * ((prv.z - mu_p) * rs_p * wv.z + bv.z);
    float p3 = fp * ((prv.w - mu_p) * rs_p * wv.w + bv.w);

    size_t idx = (size_t)t * (Dn / 4) + threadIdx.x;
    reinterpret_cast<float4*>(xres)[idx] = make_float4(o0, o1, o2, o3);

    float4 m;
    m = reinterpret_cast<const float4*>(mk)[threadIdx.x];
    reinterpret_cast<float4*>(g_xk)[idx] = make_float4(
        o0 * m.x + p0 * (1.f - m.x), o1 * m.y + p1 * (1.f - m.y),
        o2 * m.z + p2 * (1.f - m.z), o3 * m.w + p3 * (1.f - m.w));
    m = reinterpret_cast<const float4*>(mv)[threadIdx.x];
    reinterpret_cast<float4*>(g_xv)[idx] = make_float4(
        o0 * m.x + p0 * (1.f - m.x), o1 * m.y + p1 * (1.f - m.y),
        o2 * m.z + p2 * (1.f - m.z), o3 * m.w + p3 * (1.f - m.w));
    m = reinterpret_cast<const float4*>(mr)[threadIdx.x];
    reinterpret_cast<float4*>(g_xr)[idx] = make_float4(
        o0 * m.x + p0 * (1.f - m.x), o1 * m.y + p1 * (1.f - m.y),
        o2 * m.z + p2 * (1.f - m.z), o3 * m.w + p3 * (1.f - m.w));
}

// ---------------- fused LN2 + channel-mix2 (fp32 outputs) --------------------
__global__ void __launch_bounds__(256)
lnmix2_kernel(const float* __restrict__ xin,
              const float* __restrict__ w, const float* __restrict__ b,
              const float* __restrict__ mk, const float* __restrict__ mr)
{
    int t = blockIdx.x;
    float4 cur = reinterpret_cast<const float4*>(xin + (size_t)t * Dn)[threadIdx.x];
    float4 prv = make_float4(0.f, 0.f, 0.f, 0.f);
    if (t > 0) prv = reinterpret_cast<const float4*>(xin + (size_t)(t - 1) * Dn)[threadIdx.x];
    float mu_c, rs_c, mu_p, rs_p;
    ln2_stats(cur, prv, mu_c, rs_c, mu_p, rs_p);

    float4 wv = reinterpret_cast<const float4*>(w)[threadIdx.x];
    float4 bv = reinterpret_cast<const float4*>(b)[threadIdx.x];
    float o0 = (cur.x - mu_c) * rs_c * wv.x + bv.x;
    float o1 = (cur.y - mu_c) * rs_c * wv.y + bv.y;
    float o2 = (cur.z - mu_c) * rs_c * wv.z + bv.z;
    float o3 = (cur.w - mu_c) * rs_c * wv.w + bv.w;
    float fp = (t > 0) ? 1.f : 0.f;
    float p0 = fp * ((prv.x - mu_p) * rs_p * wv.x + bv.x);
    float p1 = fp * ((prv.y - mu_p) * rs_p * wv.y + bv.y);
    float p2 = fp * ((prv.z - mu_p) * rs_p * wv.z + bv.z);
    float p3 = fp * ((prv.w - mu_p) * rs_p * wv.w + bv.w);

    size_t idx = (size_t)t * (Dn / 4) + threadIdx.x;
    float4 m;
    m = reinterpret_cast<const float4*>(mk)[threadIdx.x];
    reinterpret_cast<float4*>(g_xk)[idx] = make_float4(
        o0 * m.x + p0 * (1.f - m.x), o1 * m.y + p1 * (1.f - m.y),
        o2 * m.z + p2 * (1.f - m.z), o3 * m.w + p3 * (1.f - m.w));
    m = reinterpret_cast<const float4*>(mr)[threadIdx.x];
    reinterpret_cast<float4*>(g_xr)[idx] = make_float4(
        o0 * m.x + p0 * (1.f - m.x), o1 * m.y + p1 * (1.f - m.y),
        o2 * m.z + p2 * (1.f - m.z), o3 * m.w + p3 * (1.f - m.w));
}

// ---------------- WKV scan with 8-deep load pipeline --------------------------
#define WKV_PF 8
__global__ void __launch_bounds__(128)
wkv_kernel(const float* __restrict__ td, const float* __restrict__ tf,
           const float* __restrict__ k, const float* __restrict__ v,
           const float* __restrict__ r)
{
    int d = blockIdx.x * 128 + threadIdx.x;
    if (d >= Dn) return;
    float w = -expf(td[d]);
    float u = tf[d];
    float aa = 0.f, bb = 0.f, pp = -1e30f;

    float kb[WKV_PF], vb[WKV_PF], rb[WKV_PF];
    #pragma unroll
    for (int i = 0; i < WKV_PF; i++) {
        kb[i] = k[(size_t)i * Dn + d];
        vb[i] = v[(size_t)i * Dn + d];
        rb[i] = r[(size_t)i * Dn + d];
    }

    for (int t0 = 0; t0 < Tn; t0 += WKV_PF) {
        #pragma unroll
        for (int s = 0; s < WKV_PF; s++) {
            int t = t0 + s;
            float kt = kb[s], vt = vb[s], rt = rb[s];
            int tn = t + WKV_PF;
            if (tn < Tn) {
                kb[s] = k[(size_t)tn * Dn + d];
                vb[s] = v[(size_t)tn * Dn + d];
                rb[s] = r[(size_t)tn * Dn + d];
            }
            float ww = u + kt;
            float qq = fmaxf(pp, ww);
            float e1 = __expf(pp - qq), e2 = __expf(ww - qq);
            float out = fmaf(e1, aa, e2 * vt) / fmaf(e1, bb, e2);
            float ww2 = pp + w;
            float qq2 = fmaxf(ww2, kt);
            e1 = __expf(ww2 - qq2); e2 = __expf(kt - qq2);
            aa = fmaf(e1, aa, e2 * vt);
            bb = fmaf(e1, bb, e2);
            pp = qq2;
            g_ry[(size_t)t * Dn + d] = rt * out;
        }
    }
}

// ---------------- head weight pad-copy ([D,Vn] -> [D,VP]) --------------------
__global__ void __launch_bounds__(256)
padcopy_kernel(const float* __restrict__ src, float* __restrict__ dst)
{
    int r = blockIdx.y;
    for (int c = blockIdx.x * 256 + threadIdx.x; c < VP; c += gridDim.x * 256) {
        float v = (c < Vn) ? src[(size_t)r * Vn + c] : 0.f;
        dst[(size_t)r * VP + c] = v;
    }
}

// ---------------- bf16-split mma GEMM: 256 thr, warp 64x32, 2 CTAs/SM --------
// Term-sequenced passes (hh -> hl -> lh) keep live fragments <= ~96 regs.
// C[M,N] = epi(A[M,K] @ B[K,N]); A,B fp32, split in-loop (3-term bf16).
// EPI: 0 store, 1 acc+X1, 2 relu(acc)^2, 3 sigmoid, 4 X1 + X2*acc
#define SA_H 0u
#define SA_L 10240u
#define SB_H 20480u
#define SB_L 29184u
#define STAGE_B 38144u
#define GEMM_SMEM (2 * 38144)

__device__ __forceinline__ void gemm_core(
    char* dsm,
    const float* __restrict__ A, const float* __restrict__ B,
    float* __restrict__ C, int N, int K, int ldb,
    const float* __restrict__ X1, const float* __restrict__ X2,
    int epi, bool cguard, int bm, int bn)
{
    const int tid  = threadIdx.x;
    const int lane = tid & 31;
    const int wid  = tid >> 5;       // 0..7
    const int wm   = wid >> 2;       // 0..1  (64 rows each)
    const int wn   = wid & 3;        // 0..3  (32 cols each)

    const uint32_t sbase = smem_u32(dsm);

    // A loader: 128 rows x 32 k, 256 thr -> 16 floats (two halves of 8)
    const int ar = tid >> 1, ac = (tid & 1) * 16;
    const float* Ap = A + (size_t)(bm + ar) * K + ac;
    const uint32_t aw = (uint32_t)(ar * 80 + ac * 2);
    // B loader: 32 k x 128 n, 256 thr -> 16 floats (two halves of 8)
    const int br = tid >> 3, bc = (tid & 7) * 16;
    const float* Bp = B + (size_t)br * ldb + bn + bc;
    const uint32_t bw = (uint32_t)(br * 272 + bc * 2);

    const uint32_t a_off = (uint32_t)(((lane & 15) * 40 + ((lane >> 4) << 3)) * 2);
    const uint32_t b_off = (uint32_t)(((lane & 15) * 136 + ((lane >> 4) << 3)) * 2);

    float acc[4][4][4];
    #pragma unroll
    for (int i = 0; i < 4; i++)
        #pragma unroll
        for (int j = 0; j < 4; j++)
            #pragma unroll
            for (int q = 0; q < 4; q++) acc[i][j][q] = 0.f;

    float4 st0, st1;   // 8-reg fetch staging, reused for A and B halves

    auto stash8 = [&](uint32_t dH, uint32_t dL) {
        uint32_t h[4], l[4];
        split2(st0.x, st0.y, h[0], l[0]);
        split2(st0.z, st0.w, h[1], l[1]);
        split2(st1.x, st1.y, h[2], l[2]);
        split2(st1.z, st1.w, h[3], l[3]);
        sts4(dH, h[0], h[1], h[2], h[3]);
        sts4(dL, l[0], l[1], l[2], l[3]);
    };
    auto fetchA = [&](int kc, int h) {
        const float* p = Ap + kc * 32 + h * 8;
        st0 = *reinterpret_cast<const float4*>(p);
        st1 = *reinterpret_cast<const float4*>(p + 4);
    };
    auto fetchB = [&](int kc, int h) {
        const float* p = Bp + (size_t)(kc * 32) * ldb + h * 8;
        st0 = *reinterpret_cast<const float4*>(p);
        st1 = *reinterpret_cast<const float4*>(p + 4);
    };

    // preload chunk 0
    fetchA(0, 0); stash8(sbase + SA_H + aw,      sbase + SA_L + aw);
    fetchA(0, 1); stash8(sbase + SA_H + aw + 16, sbase + SA_L + aw + 16);
    fetchB(0, 0); stash8(sbase + SB_H + bw,      sbase + SB_L + bw);
    fetchB(0, 1); stash8(sbase + SB_H + bw + 16, sbase + SB_L + bw + 16);
    __syncthreads();

    const int nch = K >> 5;
    for (int kc = 0; kc < nch; kc++) {
        const uint32_t st = sbase + (uint32_t)(kc & 1) * STAGE_B;
        const uint32_t nx = sbase + (uint32_t)((kc + 1) & 1) * STAGE_B;
        const bool more = (kc + 1 < nch);

        #pragma unroll
        for (int ks = 0; ks < 2; ks++) {
            // schedule one global fetch + one stash per ks, split across passes
            if (more && ks == 0) fetchA(kc + 1, 0);

            uint32_t bf[4][2];
            #pragma unroll
            for (int p = 0; p < 2; p++) {
                uint32_t boff = (uint32_t)((ks * 16 * 136 + wn * 32 + p * 16) * 2) + b_off;
                LDSM_X4T(st + SB_H + boff, bf[2*p][0], bf[2*p][1], bf[2*p+1][0], bf[2*p+1][1]);
            }
            uint32_t af[4][4];
            #pragma unroll
            for (int i = 0; i < 4; i++) {
                uint32_t aoff = (uint32_t)((((wm * 64 + i * 16) * 40) + ks * 16) * 2) + a_off;
                LDSM_X4(st + SA_H + aoff, af[i][0], af[i][1], af[i][2], af[i][3]);
            }
            // pass 1: hh
            #pragma unroll
            for (int i = 0; i < 4; i++)
                #pragma unroll
                for (int j = 0; j < 4; j++)
                    mma_bf16(acc[i][j], af[i], bf[j][0], bf[j][1]);

            if (more && ks == 0) stash8(nx + SA_H + aw, nx + SA_L + aw);
            if (more && ks == 0) fetchB(kc + 1, 0);
            if (more && ks == 1) fetchA(kc + 1, 1);

            // pass 2: hl (A-hi x B-lo) -- keep bf(hi) alive? no: bf reused after pass3 order swap
            uint32_t bl[4][2];
            #pragma unroll
            for (int p = 0; p < 2; p++) {
                uint32_t boff = (uint32_t)((ks * 16 * 136 + wn * 32 + p * 16) * 2) + b_off;
                LDSM_X4T(st + SB_L + boff, bl[2*p][0], bl[2*p][1], bl[2*p+1][0], bl[2*p+1][1]);
            }
            #pragma unroll
            for (int i = 0; i < 4; i++)
                #pragma unroll
                for (int j = 0; j < 4; j++)
                    mma_bf16(acc[i][j], af[i], bl[j][0], bl[j][1]);

            if (more && ks == 0) stash8(nx + SB_H + bw, nx + SB_L + bw);
            if (more && ks == 1) stash8(nx + SA_H + aw + 16, nx + SA_L + aw + 16);

            // pass 3: lh (A-lo x B-hi): reload al into af (bl dead, bf still live)
            #pragma unroll
            for (int i = 0; i < 4; i++) {
                uint32_t aoff = (uint32_t)((((wm * 64 + i * 16) * 40) + ks * 16) * 2) + a_off;
                LDSM_X4(st + SA_L + aoff, af[i][0], af[i][1], af[i][2], af[i][3]);
            }
            #pragma unroll
            for (int i = 0; i < 4; i++)
                #pragma unroll
                for (int j = 0; j < 4; j++)
                    mma_bf16(acc[i][j], af[i], bf[j][0], bf[j][1]);

            if (more && ks == 1) { fetchB(kc + 1, 1); stash8(nx + SB_H + bw + 16, nx + SB_L + bw + 16); }
        }
        __syncthreads();
    }

    // ---- epilogue ----
    #pragma unroll
    for (int i = 0; i < 4; i++) {
        #pragma unroll
        for (int j = 0; j < 4; j++) {
            int row = bm + wm * 64 + i * 16 + (lane >> 2);
            int col = bn + wn * 32 + j * 8 + ((lane & 3) << 1);
            #pragma unroll
            for (int h = 0; h < 2; h++) {
                int rr = row + h * 8;
                float v0 = acc[i][j][2 * h + 0];
                float v1 = acc[i][j][2 * h + 1];
                float* crow = C + (size_t)rr * N;
                if (epi == 1) {
                    const float* x1 = X1 + (size_t)rr * N;
                    v0 += x1[col]; v1 += x1[col + 1];
                } else if (epi == 2) {
                    float q0 = fmaxf(v0, 0.f), q1 = fmaxf(v1, 0.f);
                    v0 = q0 * q0; v1 = q1 * q1;
                } else if (epi == 3) {
                    v0 = 1.f / (1.f + expf(-v0));
                    v1 = 1.f / (1.f + expf(-v1));
                } else if (epi == 4) {
                    const float* x1 = X1 + (size_t)rr * N;
                    const float* x2 = X2 + (size_t)rr * N;
                    v0 = x1[col]     + x2[col]     * v0;
                    v1 = x1[col + 1] + x2[col + 1] * v1;
                }
                if (cguard) {
                    if (col < N)     crow[col]     = v0;
                    if (col + 1 < N) crow[col + 1] = v1;
                } else {
                    *reinterpret_cast<float2*>(crow + col) = make_float2(v0, v1);
                }
            }
        }
    }
}

// batched k/v/r GEMM: blockIdx.z selects {k: EPI0, v: EPI0, r: EPI3}
__global__ void __launch_bounds__(256, 2)
kvr_kernel(const float* Wk, const float* Wv, const float* Wr)
{
    extern __shared__ __align__(128) char dsm[];
    int z = blockIdx.z;
    const float *a, *b;
    float* c;
    int epi;
    if (z == 0)      { a = g_xk; b = Wk; c = g_k; epi = 0; }
    else if (z == 1) { a = g_xv; b = Wv; c = g_v; epi = 0; }
    else             { a = g_xr; b = Wr; c = g_r; epi = 3; }
    gemm_core(dsm, a, b, c, Dn, Dn, Dn, nullptr, nullptr,
              epi, false, blockIdx.y * 128, blockIdx.x * 128);
}

// batched channel-mix GEMM: first Hn/128 x-tiles -> kk (relu^2), rest -> rr (sigmoid)
__global__ void __launch_bounds__(256, 2)
chan_kernel(const float* CWk, const float* CWr)
{
    extern __shared__ __align__(128) char dsm[];
    int bx = blockIdx.x;
    if (bx < Hn / 128) {
        gemm_core(dsm, g_xk, CWk, g_kk, Hn, Dn, Hn, nullptr, nullptr,
                  2, false, blockIdx.y * 128, bx * 128);
    } else {
        gemm_core(dsm, g_xr, CWr, g_rr, Dn, Dn, Dn, nullptr, nullptr,
                  3, false, blockIdx.y * 128, (bx - Hn / 128) * 128);
    }
}

// single GEMM (Wo residual-add, CWv fused-update, head)
template<int EPI, bool CGUARD>
__global__ void __launch_bounds__(256, 2)
sgl_kernel(const float* A, const float* B, float* C, int N, int K, int ldb,
           const float* X1, const float* X2)
{
    extern __shared__ __align__(128) char dsm[];
    gemm_core(dsm, A, B, C, N, K, ldb, X1, X2,
              EPI, CGUARD, blockIdx.y * 128, blockIdx.x * 128);
}

// ---------------- host orchestration ----------------
extern "C" void kernel_launch(void* const* d_in, const int* in_sizes, int n_in,
                              void* d_out, int out_size)
{
    const int*   tokens   = (const int*)  d_in[0];
    const float* emb      = (const float*)d_in[1];
    const float* tm_decay = (const float*)d_in[2];
    const float* tm_first = (const float*)d_in[3];
    const float* tm_mix_k = (const float*)d_in[4];
    const float* tm_mix_v = (const float*)d_in[5];
    const float* tm_mix_r = (const float*)d_in[6];
    const float* tm_Wk    = (const float*)d_in[7];
    const float* tm_Wv    = (const float*)d_in[8];
    const float* tm_Wr    = (const float*)d_in[9];
    const float* tm_Wo    = (const float*)d_in[10];
    const float* cm_mix_k = (const float*)d_in[11];
    const float* cm_mix_r = (const float*)d_in[12];
    const float* cm_Wk    = (const float*)d_in[13];
    const float* cm_Wv    = (const float*)d_in[14];
    const float* cm_Wr    = (const float*)d_in[15];
    const float* ln0_w    = (const float*)d_in[16];
    const float* ln0_b    = (const float*)d_in[17];
    const float* ln1_w    = (const float*)d_in[18];
    const float* ln1_b    = (const float*)d_in[19];
    const float* ln2_w    = (const float*)d_in[20];
    const float* ln2_b    = (const float*)d_in[21];
    const float* lnout_w  = (const float*)d_in[22];
    const float* lnout_b  = (const float*)d_in[23];
    const float* head_W   = (const float*)d_in[24];
    float* out = (float*)d_out;

    float *x_, *xn_, *k_, *v_, *r_, *rr_, *ry_, *kk_, *hw_;
    cudaGetSymbolAddress((void**)&x_,  g_x);
    cudaGetSymbolAddress((void**)&xn_, g_xn);
    cudaGetSymbolAddress((void**)&k_,  g_k);
    cudaGetSymbolAddress((void**)&v_,  g_v);
    cudaGetSymbolAddress((void**)&r_,  g_r);
    cudaGetSymbolAddress((void**)&rr_, g_rr);
    cudaGetSymbolAddress((void**)&ry_, g_ry);
    cudaGetSymbolAddress((void**)&kk_, g_kk);
    cudaGetSymbolAddress((void**)&hw_, g_hw);

    cudaFuncSetAttribute(kvr_kernel,  cudaFuncAttributeMaxDynamicSharedMemorySize, GEMM_SMEM);
    cudaFuncSetAttribute(chan_kernel, cudaFuncAttributeMaxDynamicSharedMemorySize, GEMM_SMEM);
    cudaFuncSetAttribute(sgl_kernel<1,false>, cudaFuncAttributeMaxDynamicSharedMemorySize, GEMM_SMEM);
    cudaFuncSetAttribute(sgl_kernel<4,false>, cudaFuncAttributeMaxDynamicSharedMemorySize, GEMM_SMEM);
    cudaFuncSetAttribute(sgl_kernel<0,true>,  cudaFuncAttributeMaxDynamicSharedMemorySize, GEMM_SMEM);

    dim3 gKVR(Dn / 128, Tn / 128, 3);
    dim3 gDD(Dn / 128, Tn / 128);
    dim3 gCH(Hn / 128 + Dn / 128, Tn / 128);
    dim3 gHV(VP / 128, Tn / 128);

    padcopy_kernel<<<dim3(64, Dn), 256>>>(head_W, hw_);

    ln_kernel<<<Tn, 256>>>(emb, tokens, ln0_w, ln0_b, x_);

    for (int l = 0; l < Ln; l++) {
        const float* Wk  = tm_Wk + (size_t)l * Dn * Dn;
        const float* Wv  = tm_Wv + (size_t)l * Dn * Dn;
        const float* Wr  = tm_Wr + (size_t)l * Dn * Dn;
        const float* Wo  = tm_Wo + (size_t)l * Dn * Dn;
        const float* CWk = cm_Wk + (size_t)l * Dn * Hn;
        const float* CWv = cm_Wv + (size_t)l * Hn * Dn;
        const float* CWr = cm_Wr + (size_t)l * Dn * Dn;

        // fused LN1 + mix3: residual stream -> xn_, mixes -> g_xk/g_xv/g_xr
        lnmix3_kernel<<<Tn, 256>>>(x_, ln1_w + l * Dn, ln1_b + l * Dn,
                                   tm_mix_k + l * Dn, tm_mix_v + l * Dn,
                                   tm_mix_r + l * Dn, xn_);

        kvr_kernel<<<gKVR, 256, GEMM_SMEM>>>(Wk, Wv, Wr);

        wkv_kernel<<<Dn / 128, 128>>>(tm_decay + l * Dn, tm_first + l * Dn, k_, v_, r_);

        // x_ = xn_ + (r*y) @ Wo
        sgl_kernel<1,false><<<gDD, 256, GEMM_SMEM>>>(ry_, Wo, x_, Dn, Dn, Dn, xn_, nullptr);

        // fused LN2 + mix2
        lnmix2_kernel<<<Tn, 256>>>(x_, ln2_w + l * Dn, ln2_b + l * Dn,
                                   cm_mix_k + l * Dn, cm_mix_r + l * Dn);

        chan_kernel<<<gCH, 256, GEMM_SMEM>>>(CWk, CWr);

        // x_ = x_ + rr * (kk @ CWv)
        sgl_kernel<4,false><<<gDD, 256, GEMM_SMEM>>>(kk_, CWv, x_, Dn, Hn, Dn, x_, rr_);
    }

    ln_kernel<<<Tn, 256>>>(x_, nullptr, lnout_w, lnout_b, xn_);
    sgl_kernel<0,true><<<gHV, 256, GEMM_SMEM>>>(xn_, hw_, out, Vn, Dn, VP, nullptr, nullptr);
}

// round 13
// speedup vs baseline: 1.0283x; 1.0283x over previous
#include <cuda_runtime.h>
#include <cuda_bf16.h>
#include <math.h>
#include <stdint.h>

#define Tn 2048
#define Dn 1024
#define Hn 4096
#define Ln 8
#define Vn 50257
#define VP 50304
#define EPSn 1e-5f

// ---------------- scratch (no allocations allowed) ----------------
__device__ float g_x [Tn*Dn];
__device__ float g_xn[Tn*Dn];
__device__ float g_xk[Tn*Dn];
__device__ float g_xv[Tn*Dn];
__device__ float g_xr[Tn*Dn];
__device__ float g_k [Tn*Dn];
__device__ float g_v [Tn*Dn];
__device__ float g_r [Tn*Dn];
__device__ float g_ry[Tn*Dn];
__device__ float g_rr[Tn*Dn];
__device__ float g_kk[Tn*Hn];
__device__ float g_hw[(size_t)Dn * VP];   // padded head weight (fp32)

// ---------------- PTX helpers (portable PTX only) ----------------
__device__ __forceinline__ uint32_t smem_u32(const void* p) {
    uint32_t a;
    asm("{ .reg .u64 t; cvta.to.shared.u64 t, %1; cvt.u32.u64 %0, t; }" : "=r"(a) : "l"(p));
    return a;
}

#define LDSM_X4(addr, r0, r1, r2, r3) \
    asm volatile("ldmatrix.sync.aligned.m8n8.x4.shared.b16 {%0,%1,%2,%3}, [%4];" \
        : "=r"(r0), "=r"(r1), "=r"(r2), "=r"(r3) : "r"(addr))

#define LDSM_X4T(addr, r0, r1, r2, r3) \
    asm volatile("ldmatrix.sync.aligned.m8n8.x4.trans.shared.b16 {%0,%1,%2,%3}, [%4];" \
        : "=r"(r0), "=r"(r1), "=r"(r2), "=r"(r3) : "r"(addr))

__device__ __forceinline__ void mma_bf16(float* c, const uint32_t* a,
                                         uint32_t b0, uint32_t b1) {
    asm volatile(
        "mma.sync.aligned.m16n8k16.row.col.f32.bf16.bf16.f32 "
        "{%0,%1,%2,%3}, {%4,%5,%6,%7}, {%8,%9}, {%0,%1,%2,%3};"
        : "+f"(c[0]), "+f"(c[1]), "+f"(c[2]), "+f"(c[3])
        : "r"(a[0]), "r"(a[1]), "r"(a[2]), "r"(a[3]), "r"(b0), "r"(b1));
}

__device__ __forceinline__ void sts4(uint32_t addr, uint32_t a, uint32_t b,
                                     uint32_t c, uint32_t d) {
    asm volatile("st.shared.v4.b32 [%0], {%1,%2,%3,%4};"
                 :: "r"(addr), "r"(a), "r"(b), "r"(c), "r"(d) : "memory");
}

// split (x,y) into bf16 hi/lo pairs packed as bf16x2 words
__device__ __forceinline__ void split2(float x, float y, uint32_t& h, uint32_t& l) {
    __nv_bfloat16 hx = __float2bfloat16_rn(x);
    __nv_bfloat16 hy = __float2bfloat16_rn(y);
    float rx = x - __bfloat162float(hx);
    float ry = y - __bfloat162float(hy);
    __nv_bfloat162 hp; hp.x = hx; hp.y = hy;
    __nv_bfloat162 lp; lp.x = __float2bfloat16_rn(rx); lp.y = __float2bfloat16_rn(ry);
    h = *reinterpret_cast<uint32_t*>(&hp);
    l = *reinterpret_cast<uint32_t*>(&lp);
}

// ---------------- LayerNorm (fp32 out; optional embedding gather) ------------
__global__ void __launch_bounds__(256)
ln_kernel(const float* __restrict__ x, const int* __restrict__ tokens,
          const float* __restrict__ w, const float* __restrict__ b,
          float* __restrict__ y)
{
    __shared__ float sh0[8], sh1[8];
    int t = blockIdx.x;
    const float* row;
    if (tokens) row = x + (size_t)tokens[t] * Dn;
    else        row = x + (size_t)t * Dn;

    float4 vv = reinterpret_cast<const float4*>(row)[threadIdx.x];
    float s  = vv.x + vv.y + vv.z + vv.w;
    float s2 = vv.x*vv.x + vv.y*vv.y + vv.z*vv.z + vv.w*vv.w;
    #pragma unroll
    for (int o = 16; o > 0; o >>= 1) {
        s  += __shfl_down_sync(0xffffffffu, s,  o);
        s2 += __shfl_down_sync(0xffffffffu, s2, o);
    }
    int wid = threadIdx.x >> 5, lid = threadIdx.x & 31;
    if (lid == 0) { sh0[wid] = s; sh1[wid] = s2; }
    __syncthreads();
    if (threadIdx.x < 32) {
        s  = (lid < 8) ? sh0[lid] : 0.f;
        s2 = (lid < 8) ? sh1[lid] : 0.f;
        #pragma unroll
        for (int o = 4; o > 0; o >>= 1) {
            s  += __shfl_down_sync(0xffffffffu, s,  o);
            s2 += __shfl_down_sync(0xffffffffu, s2, o);
        }
        if (lid == 0) { sh0[0] = s; sh1[0] = s2; }
    }
    __syncthreads();
    float mu  = sh0[0] * (1.f / Dn);
    float var = sh1[0] * (1.f / Dn) - mu * mu;
    float rstd = rsqrtf(var + EPSn);

    float4 wv = reinterpret_cast<const float4*>(w)[threadIdx.x];
    float4 bv = reinterpret_cast<const float4*>(b)[threadIdx.x];
    float4 o4;
    o4.x = (vv.x - mu) * rstd * wv.x + bv.x;
    o4.y = (vv.y - mu) * rstd * wv.y + bv.y;
    o4.z = (vv.z - mu) * rstd * wv.z + bv.z;
    o4.w = (vv.w - mu) * rstd * wv.w + bv.w;
    reinterpret_cast<float4*>(y + (size_t)t * Dn)[threadIdx.x] = o4;
}

// ------------- dual-row LN reduce helper (cur & prev in one pass) ------------
__device__ __forceinline__ void ln2_stats(float4 cur, float4 prv,
                                          float& mu_c, float& rs_c,
                                          float& mu_p, float& rs_p)
{
    __shared__ float sh[4][8];
    float sc  = cur.x + cur.y + cur.z + cur.w;
    float s2c = cur.x*cur.x + cur.y*cur.y + cur.z*cur.z + cur.w*cur.w;
    float sp  = prv.x + prv.y + prv.z + prv.w;
    float s2p = prv.x*prv.x + prv.y*prv.y + prv.z*prv.z + prv.w*prv.w;
    #pragma unroll
    for (int o = 16; o > 0; o >>= 1) {
        sc  += __shfl_down_sync(0xffffffffu, sc,  o);
        s2c += __shfl_down_sync(0xffffffffu, s2c, o);
        sp  += __shfl_down_sync(0xffffffffu, sp,  o);
        s2p += __shfl_down_sync(0xffffffffu, s2p, o);
    }
    int wid = threadIdx.x >> 5, lid = threadIdx.x & 31;
    if (lid == 0) { sh[0][wid] = sc; sh[1][wid] = s2c; sh[2][wid] = sp; sh[3][wid] = s2p; }
    __syncthreads();
    if (threadIdx.x < 32) {
        sc  = (lid < 8) ? sh[0][lid] : 0.f;
        s2c = (lid < 8) ? sh[1][lid] : 0.f;
        sp  = (lid < 8) ? sh[2][lid] : 0.f;
        s2p = (lid < 8) ? sh[3][lid] : 0.f;
        #pragma unroll
        for (int o = 4; o > 0; o >>= 1) {
            sc  += __shfl_down_sync(0xffffffffu, sc,  o);
            s2c += __shfl_down_sync(0xffffffffu, s2c, o);
            sp  += __shfl_down_sync(0xffffffffu, sp,  o);
            s2p += __shfl_down_sync(0xffffffffu, s2p, o);
        }
        if (lid == 0) { sh[0][0] = sc; sh[1][0] = s2c; sh[2][0] = sp; sh[3][0] = s2p; }
    }
    __syncthreads();
    mu_c = sh[0][0] * (1.f / Dn);
    rs_c = rsqrtf(sh[1][0] * (1.f / Dn) - mu_c * mu_c + EPSn);
    mu_p = sh[2][0] * (1.f / Dn);
    rs_p = rsqrtf(sh[3][0] * (1.f / Dn) - mu_p * mu_p + EPSn);
}

// ---------------- fused LN1 + time-mix3 (fp32 outputs) -----------------------
__global__ void __launch_bounds__(256)
lnmix3_kernel(const float* __restrict__ xin,
              const float* __restrict__ w, const float* __restrict__ b,
              const float* __restrict__ mk, const float* __restrict__ mv,
              const float* __restrict__ mr, float* __restrict__ xres)
{
    int t = blockIdx.x;
    float4 cur = reinterpret_cast<const float4*>(xin + (size_t)t * Dn)[threadIdx.x];
    float4 prv = make_float4(0.f, 0.f, 0.f, 0.f);
    if (t > 0) prv = reinterpret_cast<const float4*>(xin + (size_t)(t - 1) * Dn)[threadIdx.x];
    float mu_c, rs_c, mu_p, rs_p;
    ln2_stats(cur, prv, mu_c, rs_c, mu_p, rs_p);

    float4 wv = reinterpret_cast<const float4*>(w)[threadIdx.x];
    float4 bv = reinterpret_cast<const float4*>(b)[threadIdx.x];
    float o0 = (cur.x - mu_c) * rs_c * wv.x + bv.x;
    float o1 = (cur.y - mu_c) * rs_c * wv.y + bv.y;
    float o2 = (cur.z - mu_c) * rs_c * wv.z + bv.z;
    float o3 = (cur.w - mu_c) * rs_c * wv.w + bv.w;
    float fp = (t > 0) ? 1.f : 0.f;
    float p0 = fp * ((prv.x - mu_p) * rs_p * wv.x + bv.x);
    float p1 = fp * ((prv.y - mu_p) * rs_p * wv.y + bv.y);
    float p2 = fp * ((prv.z - mu_p) * rs_p * wv.z + bv.z);
    float p3 = fp * ((prv.w - mu_p) * rs_p * wv.w + bv.w);

    size_t idx = (size_t)t * (Dn / 4) + threadIdx.x;
    reinterpret_cast<float4*>(xres)[idx] = make_float4(o0, o1, o2, o3);

    float4 m;
    m = reinterpret_cast<const float4*>(mk)[threadIdx.x];
    reinterpret_cast<float4*>(g_xk)[idx] = make_float4(
        o0 * m.x + p0 * (1.f - m.x), o1 * m.y + p1 * (1.f - m.y),
        o2 * m.z + p2 * (1.f - m.z), o3 * m.w + p3 * (1.f - m.w));
    m = reinterpret_cast<const float4*>(mv)[threadIdx.x];
    reinterpret_cast<float4*>(g_xv)[idx] = make_float4(
        o0 * m.x + p0 * (1.f - m.x), o1 * m.y + p1 * (1.f - m.y),
        o2 * m.z + p2 * (1.f - m.z), o3 * m.w + p3 * (1.f - m.w));
    m = reinterpret_cast<const float4*>(mr)[threadIdx.x];
    reinterpret_cast<float4*>(g_xr)[idx] = make_float4(
        o0 * m.x + p0 * (1.f - m.x), o1 * m.y + p1 * (1.f - m.y),
        o2 * m.z + p2 * (1.f - m.z), o3 * m.w + p3 * (1.f - m.w));
}

// ---------------- fused LN2 + channel-mix2 (fp32 outputs) --------------------
__global__ void __launch_bounds__(256)
lnmix2_kernel(const float* __restrict__ xin,
              const float* __restrict__ w, const float* __restrict__ b,
              const float* __restrict__ mk, const float* __restrict__ mr)
{
    int t = blockIdx.x;
    float4 cur = reinterpret_cast<const float4*>(xin + (size_t)t * Dn)[threadIdx.x];
    float4 prv = make_float4(0.f, 0.f, 0.f, 0.f);
    if (t > 0) prv = reinterpret_cast<const float4*>(xin + (size_t)(t - 1) * Dn)[threadIdx.x];
    float mu_c, rs_c, mu_p, rs_p;
    ln2_stats(cur, prv, mu_c, rs_c, mu_p, rs_p);

    float4 wv = reinterpret_cast<const float4*>(w)[threadIdx.x];
    float4 bv = reinterpret_cast<const float4*>(b)[threadIdx.x];
    float o0 = (cur.x - mu_c) * rs_c * wv.x + bv.x;
    float o1 = (cur.y - mu_c) * rs_c * wv.y + bv.y;
    float o2 = (cur.z - mu_c) * rs_c * wv.z + bv.z;
    float o3 = (cur.w - mu_c) * rs_c * wv.w + bv.w;
    float fp = (t > 0) ? 1.f : 0.f;
    float p0 = fp * ((prv.x - mu_p) * rs_p * wv.x + bv.x);
    float p1 = fp * ((prv.y - mu_p) * rs_p * wv.y + bv.y);
    float p2 = fp * ((prv.z - mu_p) * rs_p * wv.z + bv.z);
    float p3 = fp * ((prv.w - mu_p) * rs_p * wv.w + bv.w);

    size_t idx = (size_t)t * (Dn / 4) + threadIdx.x;
    float4 m;
    m = reinterpret_cast<const float4*>(mk)[threadIdx.x];
    reinterpret_cast<float4*>(g_xk)[idx] = make_float4(
        o0 * m.x + p0 * (1.f - m.x), o1 * m.y + p1 * (1.f - m.y),
        o2 * m.z + p2 * (1.f - m.z), o3 * m.w + p3 * (1.f - m.w));
    m = reinterpret_cast<const float4*>(mr)[threadIdx.x];
    reinterpret_cast<float4*>(g_xr)[idx] = make_float4(
        o0 * m.x + p0 * (1.f - m.x), o1 * m.y + p1 * (1.f - m.y),
        o2 * m.z + p2 * (1.f - m.z), o3 * m.w + p3 * (1.f - m.w));
}

// ---------------- WKV scan with 8-deep load pipeline --------------------------
#define WKV_PF 8
__global__ void __launch_bounds__(128)
wkv_kernel(const float* __restrict__ td, const float* __restrict__ tf,
           const float* __restrict__ k, const float* __restrict__ v,
           const float* __restrict__ r)
{
    int d = blockIdx.x * 128 + threadIdx.x;
    if (d >= Dn) return;
    float w = -expf(td[d]);
    float u = tf[d];
    float aa = 0.f, bb = 0.f, pp = -1e30f;

    float kb[WKV_PF], vb[WKV_PF], rb[WKV_PF];
    #pragma unroll
    for (int i = 0; i < WKV_PF; i++) {
        kb[i] = k[(size_t)i * Dn + d];
        vb[i] = v[(size_t)i * Dn + d];
        rb[i] = r[(size_t)i * Dn + d];
    }

    for (int t0 = 0; t0 < Tn; t0 += WKV_PF) {
        #pragma unroll
        for (int s = 0; s < WKV_PF; s++) {
            int t = t0 + s;
            float kt = kb[s], vt = vb[s], rt = rb[s];
            int tn = t + WKV_PF;
            if (tn < Tn) {
                kb[s] = k[(size_t)tn * Dn + d];
                vb[s] = v[(size_t)tn * Dn + d];
                rb[s] = r[(size_t)tn * Dn + d];
            }
            float ww = u + kt;
            float qq = fmaxf(pp, ww);
            float e1 = __expf(pp - qq), e2 = __expf(ww - qq);
            float out = fmaf(e1, aa, e2 * vt) / fmaf(e1, bb, e2);
            float ww2 = pp + w;
            float qq2 = fmaxf(ww2, kt);
            e1 = __expf(ww2 - qq2); e2 = __expf(kt - qq2);
            aa = fmaf(e1, aa, e2 * vt);
            bb = fmaf(e1, bb, e2);
            pp = qq2;
            g_ry[(size_t)t * Dn + d] = rt * out;
        }
    }
}

// ---------------- head weight pad-copy ([D,Vn] -> [D,VP]) --------------------
__global__ void __launch_bounds__(256)
padcopy_kernel(const float* __restrict__ src, float* __restrict__ dst)
{
    int r = blockIdx.y;
    for (int c = blockIdx.x * 256 + threadIdx.x; c < VP; c += gridDim.x * 256) {
        float v = (c < Vn) ? src[(size_t)r * Vn + c] : 0.f;
        dst[(size_t)r * VP + c] = v;
    }
}

// ---------------- bf16-split mma GEMM: 512 thr, warp 32x32, K-chunk 64 -------
// C[M,N] = epi(A[M,K] @ B[K,N]); A,B fp32, split in-loop (3-term bf16).
// EPI: 0 store, 1 acc+X1, 2 relu(acc)^2, 3 sigmoid, 4 X1 + X2*acc
// K must be a multiple of 64.
#define AROW 144u              // A row stride bytes (64 bf16 = 128B + 16 pad)
#define BROW 272u              // B row stride bytes (128 bf16 = 256B + 16 pad)
#define SA_H 0u
#define SA_L 18432u            // 128 * 144
#define SB_H 36864u
#define SB_L 54272u            // 36864 + 64*272
#define STAGE_B 71680u         // 54272 + 17408
#define GEMM_SMEM (2 * 71680)

__device__ __forceinline__ void gemm_core(
    char* dsm,
    const float* __restrict__ A, const float* __restrict__ B,
    float* __restrict__ C, int N, int K, int ldb,
    const float* __restrict__ X1, const float* __restrict__ X2,
    int epi, bool cguard, int bm, int bn)
{
    const int tid  = threadIdx.x;
    const int lane = tid & 31;
    const int wid  = tid >> 5;       // 0..15
    const int wm   = wid >> 2;       // 0..3   (32 rows each)
    const int wn   = wid & 3;        // 0..3   (32 cols each)

    const uint32_t sbase = smem_u32(dsm);

    // A loader: 128 rows x 64 k, 512 thr -> 16 floats (two halves of 8)
    const int ar = tid >> 2, ac = (tid & 3) * 16;
    const float* Ap = A + (size_t)(bm + ar) * K + ac;
    const uint32_t aw = (uint32_t)(ar * AROW + ac * 2);
    // B loader: 64 k x 128 n, 512 thr -> 16 floats (two halves of 8)
    const int br = tid >> 3, bc = (tid & 7) * 16;
    const float* Bp = B + (size_t)br * ldb + bn + bc;
    const uint32_t bw = (uint32_t)(br * BROW + bc * 2);

    const uint32_t a_off = (uint32_t)((lane & 15) * AROW + ((lane >> 4) << 4));
    const uint32_t b_off = (uint32_t)((lane & 15) * BROW + ((lane >> 4) << 4));

    float acc[2][4][4];
    #pragma unroll
    for (int i = 0; i < 2; i++)
        #pragma unroll
        for (int j = 0; j < 4; j++)
            #pragma unroll
            for (int q = 0; q < 4; q++) acc[i][j][q] = 0.f;

    float4 st0, st1;   // 8-float staging, reused across fetch halves

    auto stash8 = [&](uint32_t dH, uint32_t dL) {
        uint32_t h[4], l[4];
        split2(st0.x, st0.y, h[0], l[0]);
        split2(st0.z, st0.w, h[1], l[1]);
        split2(st1.x, st1.y, h[2], l[2]);
        split2(st1.z, st1.w, h[3], l[3]);
        sts4(dH, h[0], h[1], h[2], h[3]);
        sts4(dL, l[0], l[1], l[2], l[3]);
    };
    auto fetchA = [&](int kc, int h) {
        const float* p = Ap + kc * 64 + h * 8;
        st0 = *reinterpret_cast<const float4*>(p);
        st1 = *reinterpret_cast<const float4*>(p + 4);
    };
    auto fetchB = [&](int kc, int h) {
        const float* p = Bp + (size_t)(kc * 64) * ldb + h * 8;
        st0 = *reinterpret_cast<const float4*>(p);
        st1 = *reinterpret_cast<const float4*>(p + 4);
    };

    // preload chunk 0
    fetchA(0, 0); stash8(sbase + SA_H + aw,      sbase + SA_L + aw);
    fetchA(0, 1); stash8(sbase + SA_H + aw + 16, sbase + SA_L + aw + 16);
    fetchB(0, 0); stash8(sbase + SB_H + bw,      sbase + SB_L + bw);
    fetchB(0, 1); stash8(sbase + SB_H + bw + 16, sbase + SB_L + bw + 16);
    __syncthreads();

    auto compute_ks = [&](uint32_t st, int ks) {
        uint32_t bhr[4][2], blr[4][2];
        #pragma unroll
        for (int p = 0; p < 2; p++) {
            uint32_t boff = (uint32_t)(ks * 16 * BROW + (wn * 32 + p * 16) * 2) + b_off;
            LDSM_X4T(st + SB_H + boff, bhr[2*p][0], bhr[2*p][1], bhr[2*p+1][0], bhr[2*p+1][1]);
            LDSM_X4T(st + SB_L + boff, blr[2*p][0], blr[2*p][1], blr[2*p+1][0], blr[2*p+1][1]);
        }
        uint32_t ahr[2][4], alr[2][4];
        #pragma unroll
        for (int i = 0; i < 2; i++) {
            uint32_t aoff = (uint32_t)((wm * 32 + i * 16) * AROW + ks * 32) + a_off;
            LDSM_X4(st + SA_H + aoff, ahr[i][0], ahr[i][1], ahr[i][2], ahr[i][3]);
            LDSM_X4(st + SA_L + aoff, alr[i][0], alr[i][1], alr[i][2], alr[i][3]);
        }
        #pragma unroll
        for (int i = 0; i < 2; i++)
            #pragma unroll
            for (int j = 0; j < 4; j++) {
                mma_bf16(acc[i][j], ahr[i], bhr[j][0], bhr[j][1]);
                mma_bf16(acc[i][j], alr[i], bhr[j][0], bhr[j][1]);
                mma_bf16(acc[i][j], ahr[i], blr[j][0], blr[j][1]);
            }
    };

    const int nch = K >> 6;
    for (int kc = 0; kc < nch; kc++) {
        const uint32_t st = sbase + (uint32_t)(kc & 1) * STAGE_B;
        const uint32_t nx = sbase + (uint32_t)((kc + 1) & 1) * STAGE_B;
        const bool more = (kc + 1 < nch);

        if (more) fetchA(kc + 1, 0);
        compute_ks(st, 0);
        if (more) { stash8(nx + SA_H + aw, nx + SA_L + aw); fetchA(kc + 1, 1); }
        compute_ks(st, 1);
        if (more) { stash8(nx + SA_H + aw + 16, nx + SA_L + aw + 16); fetchB(kc + 1, 0); }
        compute_ks(st, 2);
        if (more) { stash8(nx + SB_H + bw, nx + SB_L + bw); fetchB(kc + 1, 1); }
        compute_ks(st, 3);
        if (more) stash8(nx + SB_H + bw + 16, nx + SB_L + bw + 16);
        __syncthreads();
    }

    // ---- epilogue ----
    #pragma unroll
    for (int i = 0; i < 2; i++) {
        #pragma unroll
        for (int j = 0; j < 4; j++) {
            int row = bm + wm * 32 + i * 16 + (lane >> 2);
            int col = bn + wn * 32 + j * 8 + ((lane & 3) << 1);
            #pragma unroll
            for (int h = 0; h < 2; h++) {
                int rr = row + h * 8;
                float v0 = acc[i][j][2 * h + 0];
                float v1 = acc[i][j][2 * h + 1];
                float* crow = C + (size_t)rr * N;
                if (epi == 1) {
                    const float* x1 = X1 + (size_t)rr * N;
                    v0 += x1[col]; v1 += x1[col + 1];
                } else if (epi == 2) {
                    float q0 = fmaxf(v0, 0.f), q1 = fmaxf(v1, 0.f);
                    v0 = q0 * q0; v1 = q1 * q1;
                } else if (epi == 3) {
                    v0 = 1.f / (1.f + expf(-v0));
                    v1 = 1.f / (1.f + expf(-v1));
                } else if (epi == 4) {
                    const float* x1 = X1 + (size_t)rr * N;
                    const float* x2 = X2 + (size_t)rr * N;
                    v0 = x1[col]     + x2[col]     * v0;
                    v1 = x1[col + 1] + x2[col + 1] * v1;
                }
                if (cguard) {
                    if (col < N)     crow[col]     = v0;
                    if (col + 1 < N) crow[col + 1] = v1;
                } else {
                    *reinterpret_cast<float2*>(crow + col) = make_float2(v0, v1);
                }
            }
        }
    }
}

// batched k/v/r GEMM: blockIdx.z selects {k: EPI0, v: EPI0, r: EPI3}
__global__ void __launch_bounds__(512, 1)
kvr_kernel(const float* Wk, const float* Wv, const float* Wr)
{
    extern __shared__ __align__(128) char dsm[];
    int z = blockIdx.z;
    const float *a, *b;
    float* c;
    int epi;
    if (z == 0)      { a = g_xk; b = Wk; c = g_k; epi = 0; }
    else if (z == 1) { a = g_xv; b = Wv; c = g_v; epi = 0; }
    else             { a = g_xr; b = Wr; c = g_r; epi = 3; }
    gemm_core(dsm, a, b, c, Dn, Dn, Dn, nullptr, nullptr,
              epi, false, blockIdx.y * 128, blockIdx.x * 128);
}

// batched channel-mix GEMM: first Hn/128 x-tiles -> kk (relu^2), rest -> rr (sigmoid)
__global__ void __launch_bounds__(512, 1)
chan_kernel(const float* CWk, const float* CWr)
{
    extern __shared__ __align__(128) char dsm[];
    int bx = blockIdx.x;
    if (bx < Hn / 128) {
        gemm_core(dsm, g_xk, CWk, g_kk, Hn, Dn, Hn, nullptr, nullptr,
                  2, false, blockIdx.y * 128, bx * 128);
    } else {
        gemm_core(dsm, g_xr, CWr, g_rr, Dn, Dn, Dn, nullptr, nullptr,
                  3, false, blockIdx.y * 128, (bx - Hn / 128) * 128);
    }
}

// single GEMM (Wo residual-add, CWv fused-update, head)
template<int EPI, bool CGUARD>
__global__ void __launch_bounds__(512, 1)
sgl_kernel(const float* A, const float* B, float* C, int N, int K, int ldb,
           const float* X1, const float* X2)
{
    extern __shared__ __align__(128) char dsm[];
    gemm_core(dsm, A, B, C, N, K, ldb, X1, X2,
              EPI, CGUARD, blockIdx.y * 128, blockIdx.x * 128);
}

// ---------------- host orchestration ----------------
extern "C" void kernel_launch(void* const* d_in, const int* in_sizes, int n_in,
                              void* d_out, int out_size)
{
    const int*   tokens   = (const int*)  d_in[0];
    const float* emb      = (const float*)d_in[1];
    const float* tm_decay = (const float*)d_in[2];
    const float* tm_first = (const float*)d_in[3];
    const float* tm_mix_k = (const float*)d_in[4];
    const float* tm_mix_v = (const float*)d_in[5];
    const float* tm_mix_r = (const float*)d_in[6];
    const float* tm_Wk    = (const float*)d_in[7];
    const float* tm_Wv    = (const float*)d_in[8];
    const float* tm_Wr    = (const float*)d_in[9];
    const float* tm_Wo    = (const float*)d_in[10];
    const float* cm_mix_k = (const float*)d_in[11];
    const float* cm_mix_r = (const float*)d_in[12];
    const float* cm_Wk    = (const float*)d_in[13];
    const float* cm_Wv    = (const float*)d_in[14];
    const float* cm_Wr    = (const float*)d_in[15];
    const float* ln0_w    = (const float*)d_in[16];
    const float* ln0_b    = (const float*)d_in[17];
    const float* ln1_w    = (const float*)d_in[18];
    const float* ln1_b    = (const float*)d_in[19];
    const float* ln2_w    = (const float*)d_in[20];
    const float* ln2_b    = (const float*)d_in[21];
    const float* lnout_w  = (const float*)d_in[22];
    const float* lnout_b  = (const float*)d_in[23];
    const float* head_W   = (const float*)d_in[24];
    float* out = (float*)d_out;

    float *x_, *xn_, *k_, *v_, *r_, *rr_, *ry_, *kk_, *hw_;
    cudaGetSymbolAddress((void**)&x_,  g_x);
    cudaGetSymbolAddress((void**)&xn_, g_xn);
    cudaGetSymbolAddress((void**)&k_,  g_k);
    cudaGetSymbolAddress((void**)&v_,  g_v);
    cudaGetSymbolAddress((void**)&r_,  g_r);
    cudaGetSymbolAddress((void**)&rr_, g_rr);
    cudaGetSymbolAddress((void**)&ry_, g_ry);
    cudaGetSymbolAddress((void**)&kk_, g_kk);
    cudaGetSymbolAddress((void**)&hw_, g_hw);

    cudaFuncSetAttribute(kvr_kernel,  cudaFuncAttributeMaxDynamicSharedMemorySize, GEMM_SMEM);
    cudaFuncSetAttribute(chan_kernel, cudaFuncAttributeMaxDynamicSharedMemorySize, GEMM_SMEM);
    cudaFuncSetAttribute(sgl_kernel<1,false>, cudaFuncAttributeMaxDynamicSharedMemorySize, GEMM_SMEM);
    cudaFuncSetAttribute(sgl_kernel<4,false>, cudaFuncAttributeMaxDynamicSharedMemorySize, GEMM_SMEM);
    cudaFuncSetAttribute(sgl_kernel<0,true>,  cudaFuncAttributeMaxDynamicSharedMemorySize, GEMM_SMEM);

    dim3 gKVR(Dn / 128, Tn / 128, 3);
    dim3 gDD(Dn / 128, Tn / 128);
    dim3 gCH(Hn / 128 + Dn / 128, Tn / 128);
    dim3 gHV(VP / 128, Tn / 128);

    padcopy_kernel<<<dim3(64, Dn), 256>>>(head_W, hw_);

    ln_kernel<<<Tn, 256>>>(emb, tokens, ln0_w, ln0_b, x_);

    for (int l = 0; l < Ln; l++) {
        const float* Wk  = tm_Wk + (size_t)l * Dn * Dn;
        const float* Wv  = tm_Wv + (size_t)l * Dn * Dn;
        const float* Wr  = tm_Wr + (size_t)l * Dn * Dn;
        const float* Wo  = tm_Wo + (size_t)l * Dn * Dn;
        const float* CWk = cm_Wk + (size_t)l * Dn * Hn;
        const float* CWv = cm_Wv + (size_t)l * Hn * Dn;
        const float* CWr = cm_Wr + (size_t)l * Dn * Dn;

        // fused LN1 + mix3: residual stream -> xn_, mixes -> g_xk/g_xv/g_xr
        lnmix3_kernel<<<Tn, 256>>>(x_, ln1_w + l * Dn, ln1_b + l * Dn,
                                   tm_mix_k + l * Dn, tm_mix_v + l * Dn,
                                   tm_mix_r + l * Dn, xn_);

        kvr_kernel<<<gKVR, 512, GEMM_SMEM>>>(Wk, Wv, Wr);

        wkv_kernel<<<Dn / 128, 128>>>(tm_decay + l * Dn, tm_first + l * Dn, k_, v_, r_);

        // x_ = xn_ + (r*y) @ Wo
        sgl_kernel<1,false><<<gDD, 512, GEMM_SMEM>>>(ry_, Wo, x_, Dn, Dn, Dn, xn_, nullptr);

        // fused LN2 + mix2
        lnmix2_kernel<<<Tn, 256>>>(x_, ln2_w + l * Dn, ln2_b + l * Dn,
                                   cm_mix_k + l * Dn, cm_mix_r + l * Dn);

        chan_kernel<<<gCH, 512, GEMM_SMEM>>>(CWk, CWr);

        // x_ = x_ + rr * (kk @ CWv)
        sgl_kernel<4,false><<<gDD, 512, GEMM_SMEM>>>(kk_, CWv, x_, Dn, Hn, Dn, x_, rr_);
    }

    ln_kernel<<<Tn, 256>>>(x_, nullptr, lnout_w, lnout_b, xn_);
    sgl_kernel<0,true><<<gHV, 512, GEMM_SMEM>>>(xn_, hw_, out, Vn, Dn, VP, nullptr, nullptr);
}

// round 15
// speedup vs baseline: 1.3463x; 1.3093x over previous
#include <cuda_runtime.h>
#include <cuda_bf16.h>
#include <math.h>
#include <stdint.h>

#define Tn 2048
#define Dn 1024
#define Hn 4096
#define Ln 8
#define Vn 50257
#define VP 50304
#define EPSn 1e-5f
#define WKV_L 128
#define WKV_NC 16

// ---------------- scratch (no allocations allowed) ----------------
__device__ float g_x [Tn*Dn];
__device__ float g_xn[Tn*Dn];
__device__ float g_xk[Tn*Dn];
__device__ float g_xv[Tn*Dn];
__device__ float g_xr[Tn*Dn];
__device__ float g_k [Tn*Dn];
__device__ float g_v [Tn*Dn];
__device__ float g_r [Tn*Dn];
__device__ float g_ry[Tn*Dn];
__device__ float g_rr[Tn*Dn];
__device__ float g_kk[Tn*Hn];
__device__ float g_hw[(size_t)Dn * VP];
// wkv chunk-scan state
__device__ float g_laa[WKV_NC*Dn], g_lbb[WKV_NC*Dn], g_lpp[WKV_NC*Dn];
__device__ float g_paa[WKV_NC*Dn], g_pbb[WKV_NC*Dn], g_ppp[WKV_NC*Dn];

// ---------------- PTX helpers (portable PTX only) ----------------
__device__ __forceinline__ uint32_t smem_u32(const void* p) {
    uint32_t a;
    asm("{ .reg .u64 t; cvta.to.shared.u64 t, %1; cvt.u32.u64 %0, t; }" : "=r"(a) : "l"(p));
    return a;
}

#define LDSM_X4(addr, r0, r1, r2, r3) \
    asm volatile("ldmatrix.sync.aligned.m8n8.x4.shared.b16 {%0,%1,%2,%3}, [%4];" \
        : "=r"(r0), "=r"(r1), "=r"(r2), "=r"(r3) : "r"(addr))

#define LDSM_X4T(addr, r0, r1, r2, r3) \
    asm volatile("ldmatrix.sync.aligned.m8n8.x4.trans.shared.b16 {%0,%1,%2,%3}, [%4];" \
        : "=r"(r0), "=r"(r1), "=r"(r2), "=r"(r3) : "r"(addr))

__device__ __forceinline__ void mma_bf16(float* c, const uint32_t* a,
                                         uint32_t b0, uint32_t b1) {
    asm volatile(
        "mma.sync.aligned.m16n8k16.row.col.f32.bf16.bf16.f32 "
        "{%0,%1,%2,%3}, {%4,%5,%6,%7}, {%8,%9}, {%0,%1,%2,%3};"
        : "+f"(c[0]), "+f"(c[1]), "+f"(c[2]), "+f"(c[3])
        : "r"(a[0]), "r"(a[1]), "r"(a[2]), "r"(a[3]), "r"(b0), "r"(b1));
}

__device__ __forceinline__ void sts4(uint32_t addr, uint32_t a, uint32_t b,
                                     uint32_t c, uint32_t d) {
    asm volatile("st.shared.v4.b32 [%0], {%1,%2,%3,%4};"
                 :: "r"(addr), "r"(a), "r"(b), "r"(c), "r"(d) : "memory");
}

// split (x,y) into bf16 hi/lo pairs packed as bf16x2 words
__device__ __forceinline__ void split2(float x, float y, uint32_t& h, uint32_t& l) {
    __nv_bfloat16 hx = __float2bfloat16_rn(x);
    __nv_bfloat16 hy = __float2bfloat16_rn(y);
    float rx = x - __bfloat162float(hx);
    float ry = y - __bfloat162float(hy);
    __nv_bfloat162 hp; hp.x = hx; hp.y = hy;
    __nv_bfloat162 lp; lp.x = __float2bfloat16_rn(rx); lp.y = __float2bfloat16_rn(ry);
    h = *reinterpret_cast<uint32_t*>(&hp);
    l = *reinterpret_cast<uint32_t*>(&lp);
}

// ---------------- LayerNorm (fp32 out; optional embedding gather) ------------
__global__ void __launch_bounds__(256)
ln_kernel(const float* __restrict__ x, const int* __restrict__ tokens,
          const float* __restrict__ w, const float* __restrict__ b,
          float* __restrict__ y)
{
    __shared__ float sh0[8], sh1[8];
    int t = blockIdx.x;
    const float* row;
    if (tokens) row = x + (size_t)tokens[t] * Dn;
    else        row = x + (size_t)t * Dn;

    float4 vv = reinterpret_cast<const float4*>(row)[threadIdx.x];
    float s  = vv.x + vv.y + vv.z + vv.w;
    float s2 = vv.x*vv.x + vv.y*vv.y + vv.z*vv.z + vv.w*vv.w;
    #pragma unroll
    for (int o = 16; o > 0; o >>= 1) {
        s  += __shfl_down_sync(0xffffffffu, s,  o);
        s2 += __shfl_down_sync(0xffffffffu, s2, o);
    }
    int wid = threadIdx.x >> 5, lid = threadIdx.x & 31;
    if (lid == 0) { sh0[wid] = s; sh1[wid] = s2; }
    __syncthreads();
    if (threadIdx.x < 32) {
        s  = (lid < 8) ? sh0[lid] : 0.f;
        s2 = (lid < 8) ? sh1[lid] : 0.f;
        #pragma unroll
        for (int o = 4; o > 0; o >>= 1) {
            s  += __shfl_down_sync(0xffffffffu, s,  o);
            s2 += __shfl_down_sync(0xffffffffu, s2, o);
        }
        if (lid == 0) { sh0[0] = s; sh1[0] = s2; }
    }
    __syncthreads();
    float mu  = sh0[0] * (1.f / Dn);
    float var = sh1[0] * (1.f / Dn) - mu * mu;
    float rstd = rsqrtf(var + EPSn);

    float4 wv = reinterpret_cast<const float4*>(w)[threadIdx.x];
    float4 bv = reinterpret_cast<const float4*>(b)[threadIdx.x];
    float4 o4;
    o4.x = (vv.x - mu) * rstd * wv.x + bv.x;
    o4.y = (vv.y - mu) * rstd * wv.y + bv.y;
    o4.z = (vv.z - mu) * rstd * wv.z + bv.z;
    o4.w = (vv.w - mu) * rstd * wv.w + bv.w;
    reinterpret_cast<float4*>(y + (size_t)t * Dn)[threadIdx.x] = o4;
}

// ------------- dual-row LN reduce helper (cur & prev in one pass) ------------
__device__ __forceinline__ void ln2_stats(float4 cur, float4 prv,
                                          float& mu_c, float& rs_c,
                                          float& mu_p, float& rs_p)
{
    __shared__ float sh[4][8];
    float sc  = cur.x + cur.y + cur.z + cur.w;
    float s2c = cur.x*cur.x + cur.y*cur.y + cur.z*cur.z + cur.w*cur.w;
    float sp  = prv.x + prv.y + prv.z + prv.w;
    float s2p = prv.x*prv.x + prv.y*prv.y + prv.z*prv.z + prv.w*prv.w;
    #pragma unroll
    for (int o = 16; o > 0; o >>= 1) {
        sc  += __shfl_down_sync(0xffffffffu, sc,  o);
        s2c += __shfl_down_sync(0xffffffffu, s2c, o);
        sp  += __shfl_down_sync(0xffffffffu, sp,  o);
        s2p += __shfl_down_sync(0xffffffffu, s2p, o);
    }
    int wid = threadIdx.x >> 5, lid = threadIdx.x & 31;
    if (lid == 0) { sh[0][wid] = sc; sh[1][wid] = s2c; sh[2][wid] = sp; sh[3][wid] = s2p; }
    __syncthreads();
    if (threadIdx.x < 32) {
        sc  = (lid < 8) ? sh[0][lid] : 0.f;
        s2c = (lid < 8) ? sh[1][lid] : 0.f;
        sp  = (lid < 8) ? sh[2][lid] : 0.f;
        s2p = (lid < 8) ? sh[3][lid] : 0.f;
        #pragma unroll
        for (int o = 4; o > 0; o >>= 1) {
            sc  += __shfl_down_sync(0xffffffffu, sc,  o);
            s2c += __shfl_down_sync(0xffffffffu, s2c, o);
            sp  += __shfl_down_sync(0xffffffffu, sp,  o);
            s2p += __shfl_down_sync(0xffffffffu, s2p, o);
        }
        if (lid == 0) { sh[0][0] = sc; sh[1][0] = s2c; sh[2][0] = sp; sh[3][0] = s2p; }
    }
    __syncthreads();
    mu_c = sh[0][0] * (1.f / Dn);
    rs_c = rsqrtf(sh[1][0] * (1.f / Dn) - mu_c * mu_c + EPSn);
    mu_p = sh[2][0] * (1.f / Dn);
    rs_p = rsqrtf(sh[3][0] * (1.f / Dn) - mu_p * mu_p + EPSn);
}

// ---------------- fused LN1 + time-mix3 (fp32 outputs) -----------------------
__global__ void __launch_bounds__(256)
lnmix3_kernel(const float* __restrict__ xin,
              const float* __restrict__ w, const float* __restrict__ b,
              const float* __restrict__ mk, const float* __restrict__ mv,
              const float* __restrict__ mr, float* __restrict__ xres)
{
    int t = blockIdx.x;
    float4 cur = reinterpret_cast<const float4*>(xin + (size_t)t * Dn)[threadIdx.x];
    float4 prv = make_float4(0.f, 0.f, 0.f, 0.f);
    if (t > 0) prv = reinterpret_cast<const float4*>(xin + (size_t)(t - 1) * Dn)[threadIdx.x];
    float mu_c, rs_c, mu_p, rs_p;
    ln2_stats(cur, prv, mu_c, rs_c, mu_p, rs_p);

    float4 wv = reinterpret_cast<const float4*>(w)[threadIdx.x];
    float4 bv = reinterpret_cast<const float4*>(b)[threadIdx.x];
    float o0 = (cur.x - mu_c) * rs_c * wv.x + bv.x;
    float o1 = (cur.y - mu_c) * rs_c * wv.y + bv.y;
    float o2 = (cur.z - mu_c) * rs_c * wv.z + bv.z;
    float o3 = (cur.w - mu_c) * rs_c * wv.w + bv.w;
    float fp = (t > 0) ? 1.f : 0.f;
    float p0 = fp * ((prv.x - mu_p) * rs_p * wv.x + bv.x);
    float p1 = fp * ((prv.y - mu_p) * rs_p * wv.y + bv.y);
    float p2 = fp * ((prv.z - mu_p) * rs_p * wv.z + bv.z);
    float p3 = fp * ((prv.w - mu_p) * rs_p * wv.w + bv.w);

    size_t idx = (size_t)t * (Dn / 4) + threadIdx.x;
    reinterpret_cast<float4*>(xres)[idx] = make_float4(o0, o1, o2, o3);

    float4 m;
    m = reinterpret_cast<const float4*>(mk)[threadIdx.x];
    reinterpret_cast<float4*>(g_xk)[idx] = make_float4(
        o0 * m.x + p0 * (1.f - m.x), o1 * m.y + p1 * (1.f - m.y),
        o2 * m.z + p2 * (1.f - m.z), o3 * m.w + p3 * (1.f - m.w));
    m = reinterpret_cast<const float4*>(mv)[threadIdx.x];
    reinterpret_cast<float4*>(g_xv)[idx] = make_float4(
        o0 * m.x + p0 * (1.f - m.x), o1 * m.y + p1 * (1.f - m.y),
        o2 * m.z + p2 * (1.f - m.z), o3 * m.w + p3 * (1.f - m.w));
    m = reinterpret_cast<const float4*>(mr)[threadIdx.x];
    reinterpret_cast<float4*>(g_xr)[idx] = make_float4(
        o0 * m.x + p0 * (1.f - m.x), o1 * m.y + p1 * (1.f - m.y),
        o2 * m.z + p2 * (1.f - m.z), o3 * m.w + p3 * (1.f - m.w));
}

// ---------------- fused LN2 + channel-mix2 (fp32 outputs) --------------------
__global__ void __launch_bounds__(256)
lnmix2_kernel(const float* __restrict__ xin,
              const float* __restrict__ w, const float* __restrict__ b,
              const float* __restrict__ mk, const float* __restrict__ mr)
{
    int t = blockIdx.x;
    float4 cur = reinterpret_cast<const float4*>(xin + (size_t)t * Dn)[threadIdx.x];
    float4 prv = make_float4(0.f, 0.f, 0.f, 0.f);
    if (t > 0) prv = reinterpret_cast<const float4*>(xin + (size_t)(t - 1) * Dn)[threadIdx.x];
    float mu_c, rs_c, mu_p, rs_p;
    ln2_stats(cur, prv, mu_c, rs_c, mu_p, rs_p);

    float4 wv = reinterpret_cast<const float4*>(w)[threadIdx.x];
    float4 bv = reinterpret_cast<const float4*>(b)[threadIdx.x];
    float o0 = (cur.x - mu_c) * rs_c * wv.x + bv.x;
    float o1 = (cur.y - mu_c) * rs_c * wv.y + bv.y;
    float o2 = (cur.z - mu_c) * rs_c * wv.z + bv.z;
    float o3 = (cur.w - mu_c) * rs_c * wv.w + bv.w;
    float fp = (t > 0) ? 1.f : 0.f;
    float p0 = fp * ((prv.x - mu_p) * rs_p * wv.x + bv.x);
    float p1 = fp * ((prv.y - mu_p) * rs_p * wv.y + bv.y);
    float p2 = fp * ((prv.z - mu_p) * rs_p * wv.z + bv.z);
    float p3 = fp * ((prv.w - mu_p) * rs_p * wv.w + bv.w);

    size_t idx = (size_t)t * (Dn / 4) + threadIdx.x;
    float4 m;
    m = reinterpret_cast<const float4*>(mk)[threadIdx.x];
    reinterpret_cast<float4*>(g_xk)[idx] = make_float4(
        o0 * m.x + p0 * (1.f - m.x), o1 * m.y + p1 * (1.f - m.y),
        o2 * m.z + p2 * (1.f - m.z), o3 * m.w + p3 * (1.f - m.w));
    m = reinterpret_cast<const float4*>(mr)[threadIdx.x];
    reinterpret_cast<float4*>(g_xr)[idx] = make_float4(
        o0 * m.x + p0 * (1.f - m.x), o1 * m.y + p1 * (1.f - m.y),
        o2 * m.z + p2 * (1.f - m.z), o3 * m.w + p3 * (1.f - m.w));
}

// ---------------- chunk-parallel WKV scan (3 passes) ---------------------------
__global__ void __launch_bounds__(128)
wkv_p1_kernel(const float* __restrict__ td,
              const float* __restrict__ k, const float* __restrict__ v)
{
    int d = blockIdx.x * 128 + threadIdx.x;
    int c = blockIdx.y;
    int t0 = c * WKV_L;
    float w = -expf(td[d]);
    float aa = 0.f, bb = 0.f, pp = -1e30f;

    float kb[8], vb[8];
    #pragma unroll
    for (int i = 0; i < 8; i++) {
        kb[i] = k[(size_t)(t0 + i) * Dn + d];
        vb[i] = v[(size_t)(t0 + i) * Dn + d];
    }
    for (int tt = 0; tt < WKV_L; tt += 8) {
        #pragma unroll
        for (int s = 0; s < 8; s++) {
            float kt = kb[s], vt = vb[s];
            int tn = tt + s + 8;
            if (tn < WKV_L) {
                kb[s] = k[(size_t)(t0 + tn) * Dn + d];
                vb[s] = v[(size_t)(t0 + tn) * Dn + d];
            }
            float ww2 = pp + w;
            float qq2 = fmaxf(ww2, kt);
            float e1 = __expf(ww2 - qq2), e2 = __expf(kt - qq2);
            aa = fmaf(e1, aa, e2 * vt);
            bb = fmaf(e1, bb, e2);
            pp = qq2;
        }
    }
    g_laa[c * Dn + d] = aa;
    g_lbb[c * Dn + d] = bb;
    g_lpp[c * Dn + d] = pp;
}

__global__ void __launch_bounds__(128)
wkv_p2_kernel(const float* __restrict__ td)
{
    int d = blockIdx.x * 128 + threadIdx.x;
    float w = -expf(td[d]);
    float caa = 0.f, cbb = 0.f, cpp = -1e30f;
    for (int c = 0; c < WKV_NC; c++) {
        g_paa[c * Dn + d] = caa;
        g_pbb[c * Dn + d] = cbb;
        g_ppp[c * Dn + d] = cpp;
        float pre = cpp + (float)WKV_L * w;
        float lpp = g_lpp[c * Dn + d];
        float q = fmaxf(pre, lpp);
        float e1 = __expf(pre - q), e2 = __expf(lpp - q);
        caa = fmaf(e1, caa, e2 * g_laa[c * Dn + d]);
        cbb = fmaf(e1, cbb, e2 * g_lbb[c * Dn + d]);
        cpp = q;
    }
}

__global__ void __launch_bounds__(128)
wkv_p3_kernel(const float* __restrict__ td, const float* __restrict__ tf,
              const float* __restrict__ k, const float* __restrict__ v,
              const float* __restrict__ r)
{
    int d = blockIdx.x * 128 + threadIdx.x;
    int c = blockIdx.y;
    int t0 = c * WKV_L;
    float w = -expf(td[d]);
    float u = tf[d];
    float aa = g_paa[c * Dn + d];
    float bb = g_pbb[c * Dn + d];
    float pp = g_ppp[c * Dn + d];

    float kb[8], vb[8], rb[8];
    #pragma unroll
    for (int i = 0; i < 8; i++) {
        kb[i] = k[(size_t)(t0 + i) * Dn + d];
        vb[i] = v[(size_t)(t0 + i) * Dn + d];
        rb[i] = r[(size_t)(t0 + i) * Dn + d];
    }
    for (int tt = 0; tt < WKV_L; tt += 8) {
        #pragma unroll
        for (int s = 0; s < 8; s++) {
            int t = t0 + tt + s;
            float kt = kb[s], vt = vb[s], rt = rb[s];
            int tn = tt + s + 8;
            if (tn < WKV_L) {
                kb[s] = k[(size_t)(t0 + tn) * Dn + d];
                vb[s] = v[(size_t)(t0 + tn) * Dn + d];
                rb[s] = r[(size_t)(t0 + tn) * Dn + d];
            }
            float ww = u + kt;
            float qq = fmaxf(pp, ww);
            float e1 = __expf(pp - qq), e2 = __expf(ww - qq);
            float out = fmaf(e1, aa, e2 * vt) / fmaf(e1, bb, e2);
            float ww2 = pp + w;
            float qq2 = fmaxf(ww2, kt);
            e1 = __expf(ww2 - qq2); e2 = __expf(kt - qq2);
            aa = fmaf(e1, aa, e2 * vt);
            bb = fmaf(e1, bb, e2);
            pp = qq2;
            g_ry[(size_t)t * Dn + d] = rt * out;
        }
    }
}

// ---------------- head weight pad-copy ([D,Vn] -> [D,VP]) --------------------
__global__ void __launch_bounds__(256)
padcopy_kernel(const float* __restrict__ src, float* __restrict__ dst)
{
    int r = blockIdx.y;
    for (int c = blockIdx.x * 256 + threadIdx.x; c < VP; c += gridDim.x * 256) {
        float v = (c < Vn) ? src[(size_t)r * Vn + c] : 0.f;
        dst[(size_t)r * VP + c] = v;
    }
}

// ---------------- bf16-split mma GEMM core: 512 threads, 16 warps ------------
// (exact R11 configuration — proven best GEMM)
// smode: 0 = vector float2 store (even row stride), 1 = scalar unguarded,
//        2 = scalar col-guarded (last head tile)
#define SA_H 0u
#define SA_L 10240u
#define SB_H 20480u
#define SB_L 29184u
#define STAGE_B 38144u
#define GEMM_SMEM (2 * 38144)

__device__ __forceinline__ void gemm_core(
    char* dsm,
    const float* __restrict__ A, const float* __restrict__ B,
    float* __restrict__ C, int N, int K, int ldb,
    const float* __restrict__ X1, const float* __restrict__ X2,
    int epi, int smode, int bm, int bn)
{
    const int tid  = threadIdx.x;
    const int lane = tid & 31;
    const int wid  = tid >> 5;       // 0..15
    const int wm   = wid >> 2;       // 0..3   (32 rows each)
    const int wn   = wid & 3;        // 0..3   (32 cols each)

    const uint32_t sbase = smem_u32(dsm);

    const int ar = tid >> 2, ac = (tid & 3) * 8;
    const float* Ap = A + (size_t)(bm + ar) * K + ac;
    const uint32_t aw = (uint32_t)(ar * 80 + ac * 2);
    const int br = tid >> 4, bc = (tid & 15) * 8;
    const float* Bp = B + (size_t)br * ldb + bn + bc;
    const uint32_t bw = (uint32_t)(br * 272 + bc * 2);

    const uint32_t a_off = (uint32_t)(((lane & 15) * 40 + ((lane >> 4) << 3)) * 2);
    const uint32_t b_off = (uint32_t)(((lane & 15) * 136 + ((lane >> 4) << 3)) * 2);

    float acc[2][4][4];
    #pragma unroll
    for (int i = 0; i < 2; i++)
        #pragma unroll
        for (int j = 0; j < 4; j++)
            #pragma unroll
            for (int q = 0; q < 4; q++) acc[i][j][q] = 0.f;

    float4 ra0, ra1, rb0, rb1;

    auto fetch = [&](int kc) {
        const float* ap = Ap + kc * 32;
        const float* bp = Bp + (size_t)(kc * 32) * ldb;
        ra0 = *reinterpret_cast<const float4*>(ap);
        ra1 = *reinterpret_cast<const float4*>(ap + 4);
        rb0 = *reinterpret_cast<const float4*>(bp);
        rb1 = *reinterpret_cast<const float4*>(bp + 4);
    };
    auto stash = [&](uint32_t st) {
        uint32_t h[4], l[4];
        split2(ra0.x, ra0.y, h[0], l[0]);
        split2(ra0.z, ra0.w, h[1], l[1]);
        split2(ra1.x, ra1.y, h[2], l[2]);
        split2(ra1.z, ra1.w, h[3], l[3]);
        sts4(st + SA_H + aw, h[0], h[1], h[2], h[3]);
        sts4(st + SA_L + aw, l[0], l[1], l[2], l[3]);
        split2(rb0.x, rb0.y, h[0], l[0]);
        split2(rb0.z, rb0.w, h[1], l[1]);
        split2(rb1.x, rb1.y, h[2], l[2]);
        split2(rb1.z, rb1.w, h[3], l[3]);
        sts4(st + SB_H + bw, h[0], h[1], h[2], h[3]);
        sts4(st + SB_L + bw, l[0], l[1], l[2], l[3]);
    };

    fetch(0);
    stash(sbase);
    __syncthreads();

    const int nch = K >> 5;
    for (int kc = 0; kc < nch; kc++) {
        const uint32_t st = sbase + (uint32_t)(kc & 1) * STAGE_B;

        if (kc + 1 < nch) fetch(kc + 1);

        #pragma unroll
        for (int ks = 0; ks < 2; ks++) {
            uint32_t bhr[4][2], blr[4][2];
            #pragma unroll
            for (int p = 0; p < 2; p++) {
                uint32_t boff = (uint32_t)((ks * 16 * 136 + wn * 32 + p * 16) * 2) + b_off;
                LDSM_X4T(st + SB_H + boff, bhr[2*p][0], bhr[2*p][1], bhr[2*p+1][0], bhr[2*p+1][1]);
                LDSM_X4T(st + SB_L + boff, blr[2*p][0], blr[2*p][1], blr[2*p+1][0], blr[2*p+1][1]);
            }
            uint32_t ahr[2][4], alr[2][4];
            #pragma unroll
            for (int i = 0; i < 2; i++) {
                uint32_t aoff = (uint32_t)((((wm * 32 + i * 16) * 40) + ks * 16) * 2) + a_off;
                LDSM_X4(st + SA_H + aoff, ahr[i][0], ahr[i][1], ahr[i][2], ahr[i][3]);
                LDSM_X4(st + SA_L + aoff, alr[i][0], alr[i][1], alr[i][2], alr[i][3]);
            }
            #pragma unroll
            for (int i = 0; i < 2; i++)
                #pragma unroll
                for (int j = 0; j < 4; j++) {
                    mma_bf16(acc[i][j], ahr[i], bhr[j][0], bhr[j][1]);
                    mma_bf16(acc[i][j], alr[i], bhr[j][0], bhr[j][1]);
                    mma_bf16(acc[i][j], ahr[i], blr[j][0], blr[j][1]);
                }
        }

        if (kc + 1 < nch)
            stash(sbase + (uint32_t)((kc + 1) & 1) * STAGE_B);
        __syncthreads();
    }

    // ---- epilogue ----
    #pragma unroll
    for (int i = 0; i < 2; i++) {
        #pragma unroll
        for (int j = 0; j < 4; j++) {
            int row = bm + wm * 32 + i * 16 + (lane >> 2);
            int col = bn + wn * 32 + j * 8 + ((lane & 3) << 1);
            #pragma unroll
            for (int h = 0; h < 2; h++) {
                int rr = row + h * 8;
                float v0 = acc[i][j][2 * h + 0];
                float v1 = acc[i][j][2 * h + 1];
                float* crow = C + (size_t)rr * N;
                if (epi == 1) {
                    const float* x1 = X1 + (size_t)rr * N;
                    v0 += x1[col]; v1 += x1[col + 1];
                } else if (epi == 2) {
                    float q0 = fmaxf(v0, 0.f), q1 = fmaxf(v1, 0.f);
                    v0 = q0 * q0; v1 = q1 * q1;
                } else if (epi == 3) {
                    v0 = 1.f / (1.f + expf(-v0));
                    v1 = 1.f / (1.f + expf(-v1));
                } else if (epi == 4) {
                    const float* x1 = X1 + (size_t)rr * N;
                    const float* x2 = X2 + (size_t)rr * N;
                    v0 = x1[col]     + x2[col]     * v0;
                    v1 = x1[col + 1] + x2[col + 1] * v1;
                }
                if (smode == 0) {
                    *reinterpret_cast<float2*>(crow + col) = make_float2(v0, v1);
                } else if (smode == 1) {
                    crow[col]     = v0;
                    crow[col + 1] = v1;
                } else {
                    if (col < N)     crow[col]     = v0;
                    if (col + 1 < N) crow[col + 1] = v1;
                }
            }
        }
    }
}

// batched k/v/r GEMM: blockIdx.z selects {k: EPI0, v: EPI0, r: EPI3}
__global__ void __launch_bounds__(512, 1)
kvr_kernel(const float* Wk, const float* Wv, const float* Wr)
{
    extern __shared__ __align__(128) char dsm[];
    int z = blockIdx.z;
    const float *a, *b;
    float* c;
    int epi;
    if (z == 0)      { a = g_xk; b = Wk; c = g_k; epi = 0; }
    else if (z == 1) { a = g_xv; b = Wv; c = g_v; epi = 0; }
    else             { a = g_xr; b = Wr; c = g_r; epi = 3; }
    gemm_core(dsm, a, b, c, Dn, Dn, Dn, nullptr, nullptr,
              epi, 0, blockIdx.y * 128, blockIdx.x * 128);
}

// batched channel-mix GEMM
__global__ void __launch_bounds__(512, 1)
chan_kernel(const float* CWk, const float* CWr)
{
    extern __shared__ __align__(128) char dsm[];
    int bx = blockIdx.x;
    if (bx < Hn / 128) {
        gemm_core(dsm, g_xk, CWk, g_kk, Hn, Dn, Hn, nullptr, nullptr,
                  2, 0, blockIdx.y * 128, bx * 128);
    } else {
        gemm_core(dsm, g_xr, CWr, g_rr, Dn, Dn, Dn, nullptr, nullptr,
                  3, 0, blockIdx.y * 128, (bx - Hn / 128) * 128);
    }
}

// single GEMM (Wo residual-add, CWv fused-update)
template<int EPI>
__global__ void __launch_bounds__(512, 1)
sgl_kernel(const float* A, const float* B, float* C, int N, int K, int ldb,
           const float* X1, const float* X2)
{
    extern __shared__ __align__(128) char dsm[];
    gemm_core(dsm, A, B, C, N, K, ldb, X1, X2,
              EPI, 0, blockIdx.y * 128, blockIdx.x * 128);
}

// head GEMM: odd N -> scalar stores; guard only the straddling x-tile
__global__ void __launch_bounds__(512, 1)
head_kernel(const float* A, const float* B, float* C, int N, int K, int ldb)
{
    extern __shared__ __align__(128) char dsm[];
    int bn = blockIdx.x * 128;
    gemm_core(dsm, A, B, C, N, K, ldb, nullptr, nullptr,
              0, (bn + 128 > N) ? 2 : 1, blockIdx.y * 128, bn);
}

// ---------------- host orchestration ----------------
extern "C" void kernel_launch(void* const* d_in, const int* in_sizes, int n_in,
                              void* d_out, int out_size)
{
    const int*   tokens   = (const int*)  d_in[0];
    const float* emb      = (const float*)d_in[1];
    const float* tm_decay = (const float*)d_in[2];
    const float* tm_first = (const float*)d_in[3];
    const float* tm_mix_k = (const float*)d_in[4];
    const float* tm_mix_v = (const float*)d_in[5];
    const float* tm_mix_r = (const float*)d_in[6];
    const float* tm_Wk    = (const float*)d_in[7];
    const float* tm_Wv    = (const float*)d_in[8];
    const float* tm_Wr    = (const float*)d_in[9];
    const float* tm_Wo    = (const float*)d_in[10];
    const float* cm_mix_k = (const float*)d_in[11];
    const float* cm_mix_r = (const float*)d_in[12];
    const float* cm_Wk    = (const float*)d_in[13];
    const float* cm_Wv    = (const float*)d_in[14];
    const float* cm_Wr    = (const float*)d_in[15];
    const float* ln0_w    = (const float*)d_in[16];
    const float* ln0_b    = (const float*)d_in[17];
    const float* ln1_w    = (const float*)d_in[18];
    const float* ln1_b    = (const float*)d_in[19];
    const float* ln2_w    = (const float*)d_in[20];
    const float* ln2_b    = (const float*)d_in[21];
    const float* lnout_w  = (const float*)d_in[22];
    const float* lnout_b  = (const float*)d_in[23];
    const float* head_W   = (const float*)d_in[24];
    float* out = (float*)d_out;

    float *x_, *xn_, *k_, *v_, *r_, *rr_, *ry_, *kk_, *hw_;
    cudaGetSymbolAddress((void**)&x_,  g_x);
    cudaGetSymbolAddress((void**)&xn_, g_xn);
    cudaGetSymbolAddress((void**)&k_,  g_k);
    cudaGetSymbolAddress((void**)&v_,  g_v);
    cudaGetSymbolAddress((void**)&r_,  g_r);
    cudaGetSymbolAddress((void**)&rr_, g_rr);
    cudaGetSymbolAddress((void**)&ry_, g_ry);
    cudaGetSymbolAddress((void**)&kk_, g_kk);
    cudaGetSymbolAddress((void**)&hw_, g_hw);

    cudaFuncSetAttribute(kvr_kernel,  cudaFuncAttributeMaxDynamicSharedMemorySize, GEMM_SMEM);
    cudaFuncSetAttribute(chan_kernel, cudaFuncAttributeMaxDynamicSharedMemorySize, GEMM_SMEM);
    cudaFuncSetAttribute(sgl_kernel<1>, cudaFuncAttributeMaxDynamicSharedMemorySize, GEMM_SMEM);
    cudaFuncSetAttribute(sgl_kernel<4>, cudaFuncAttributeMaxDynamicSharedMemorySize, GEMM_SMEM);
    cudaFuncSetAttribute(head_kernel,   cudaFuncAttributeMaxDynamicSharedMemorySize, GEMM_SMEM);

    dim3 gKVR(Dn / 128, Tn / 128, 3);
    dim3 gDD(Dn / 128, Tn / 128);
    dim3 gCH(Hn / 128 + Dn / 128, Tn / 128);
    dim3 gHV(VP / 128, Tn / 128);
    dim3 gWKV(Dn / 128, WKV_NC);

    padcopy_kernel<<<dim3(64, Dn), 256>>>(head_W, hw_);

    ln_kernel<<<Tn, 256>>>(emb, tokens, ln0_w, ln0_b, x_);

    for (int l = 0; l < Ln; l++) {
        const float* Wk  = tm_Wk + (size_t)l * Dn * Dn;
        const float* Wv  = tm_Wv + (size_t)l * Dn * Dn;
        const float* Wr  = tm_Wr + (size_t)l * Dn * Dn;
        const float* Wo  = tm_Wo + (size_t)l * Dn * Dn;
        const float* CWk = cm_Wk + (size_t)l * Dn * Hn;
        const float* CWv = cm_Wv + (size_t)l * Hn * Dn;
        const float* CWr = cm_Wr + (size_t)l * Dn * Dn;

        lnmix3_kernel<<<Tn, 256>>>(x_, ln1_w + l * Dn, ln1_b + l * Dn,
                                   tm_mix_k + l * Dn, tm_mix_v + l * Dn,
                                   tm_mix_r + l * Dn, xn_);

        kvr_kernel<<<gKVR, 512, GEMM_SMEM>>>(Wk, Wv, Wr);

        // chunk-parallel WKV: local states -> carry scan -> replay with outputs
        wkv_p1_kernel<<<gWKV, 128>>>(tm_decay + l * Dn, k_, v_);
        wkv_p2_kernel<<<Dn / 128, 128>>>(tm_decay + l * Dn);
        wkv_p3_kernel<<<gWKV, 128>>>(tm_decay + l * Dn, tm_first + l * Dn, k_, v_, r_);

        // x_ = xn_ + (r*y) @ Wo
        sgl_kernel<1><<<gDD, 512, GEMM_SMEM>>>(ry_, Wo, x_, Dn, Dn, Dn, xn_, nullptr);

        lnmix2_kernel<<<Tn, 256>>>(x_, ln2_w + l * Dn, ln2_b + l * Dn,
                                   cm_mix_k + l * Dn, cm_mix_r + l * Dn);

        chan_kernel<<<gCH, 512, GEMM_SMEM>>>(CWk, CWr);

        // x_ = x_ + rr * (kk @ CWv)
        sgl_kernel<4><<<gDD, 512, GEMM_SMEM>>>(kk_, CWv, x_, Dn, Hn, Dn, x_, rr_);
    }

    ln_kernel<<<Tn, 256>>>(x_, nullptr, lnout_w, lnout_b, xn_);
    head_kernel<<<gHV, 512, GEMM_SMEM>>>(xn_, hw_, out, Vn, Dn, VP);
}